// round 17
// baseline (speedup 1.0000x reference)
#include <cuda_runtime.h>
#include <cuda_bf16.h>
#include <stdint.h>
#include <math.h>

typedef unsigned int u32;

#define NN 20000
#define EE 320000
#define DD 128
#define HH 3
#define HD (HH*DD)      /* 384 */
#define LL 3
#define GG 64
#define TWO_D (2*DD)    /* 256 */
#define NEG_SLOPE 0.2f

// ---------------- scratch (device globals; no allocation allowed) ----------------
__device__ float g_h[(size_t)NN*HD];
__device__ float g_featA[(size_t)NN*DD];
__device__ float g_featB[(size_t)NN*DD];
__device__ float g_gate[NN];
__device__ float g_sns[NN*HH];
__device__ float g_snd[NN*HH];
__device__ int   g_deg[NN];
__device__ int   g_rowptr[NN+1];
__device__ int   g_cursor[NN];
__device__ int   g_csrsrc[EE];
__device__ int   g_gstart[GG];
__device__ int   g_gend[GG];

// bf16 split buffers
__device__ __nv_bfloat16 g_fhiA[(size_t)NN*DD];
__device__ __nv_bfloat16 g_floA[(size_t)NN*DD];
__device__ __nv_bfloat16 g_fhiB[(size_t)NN*DD];
__device__ __nv_bfloat16 g_floB[(size_t)NN*DD];
__device__ __nv_bfloat16 g_agghi[(size_t)NN*HD];
__device__ __nv_bfloat16 g_agglo[(size_t)NN*HD];
__device__ __nv_bfloat16 g_wfchi[(size_t)LL*HD*DD];
__device__ __nv_bfloat16 g_wfclo[(size_t)LL*HD*DD];
__device__ __nv_bfloat16 g_wtrhi[(size_t)LL*DD*HD];
__device__ __nv_bfloat16 g_wtrlo[(size_t)LL*DD*HD];
__device__ __nv_bfloat16 g_wp1hi[(size_t)LL*TWO_D*DD];
__device__ __nv_bfloat16 g_wp1lo[(size_t)LL*TWO_D*DD];

__device__ __forceinline__ void split_bf16(float v, __nv_bfloat16& hi, __nv_bfloat16& lo) {
    hi = __float2bfloat16_rn(v);
    lo = __float2bfloat16_rn(v - __bfloat162float(hi));
}

// ---------------- setup kernels ----------------
__global__ void copy_split_kernel(const float* __restrict__ srcp, float* __restrict__ out) {
    int i = blockIdx.x*blockDim.x + threadIdx.x;
    if (i < NN*DD) {
        float v = srcp[i];
        g_featA[i] = v;
        __nv_bfloat16 hi, lo; split_bf16(v, hi, lo);
        g_fhiA[i] = hi; g_floA[i] = lo;
    }
    if (i < NN*HH) { g_sns[i] = 0.f; g_snd[i] = 0.f; }
    if (i < NN)    { g_gate[i] = 0.f; g_deg[i] = 0; }
    if (i < GG*DD) out[i] = 0.f;
    if (i < GG)    { g_gstart[i] = NN; g_gend[i] = 0; }
}

__global__ void convw_kernel(const float* __restrict__ fc, const float* __restrict__ tr,
                             const float* __restrict__ p1) {
    const int NFC = LL*HD*DD;
    const int NTR = LL*DD*HD;
    const int NP1 = LL*TWO_D*DD;
    int i = blockIdx.x*blockDim.x + threadIdx.x;
    if (i < NFC) {
        __nv_bfloat16 h, l; split_bf16(fc[i], h, l);
        g_wfchi[i] = h; g_wfclo[i] = l;
    } else if (i < NFC + NTR) {
        int j = i - NFC;
        __nv_bfloat16 h, l; split_bf16(tr[j], h, l);
        g_wtrhi[j] = h; g_wtrlo[j] = l;
    } else if (i < NFC + NTR + NP1) {
        int j = i - NFC - NTR;
        __nv_bfloat16 h, l; split_bf16(p1[j], h, l);
        g_wp1hi[j] = h; g_wp1lo[j] = l;
    }
}

__global__ void histgb_kernel(const int* __restrict__ dst, const int* __restrict__ gid) {
    int i = blockIdx.x*blockDim.x + threadIdx.x;
    if (i < EE) atomicAdd(&g_deg[dst[i]], 1);
    if (i < NN) {
        int g = gid[i];
        atomicMin(&g_gstart[g], i);
        atomicMax(&g_gend[g], i + 1);
    }
}

// ---- single-block prefix scan, smem-staged, coalesced IO ----
#define SCAN_CH 20
#define SCAN_SMEM ((NN + 1024) * (int)sizeof(int))
__global__ void scan_kernel() {
    extern __shared__ int sm[];
    int* vals = sm;
    int* part = sm + NN;
    const int t = threadIdx.x;

    for (int j = t; j < NN; j += 1024) vals[j] = g_deg[j];
    __syncthreads();

    const int base = t * SCAN_CH;
    int s = 0;
#pragma unroll
    for (int i = 0; i < SCAN_CH; i++) {
        int idx = base + i;
        if (idx < NN) {
            int v = vals[idx];
            vals[idx] = s;
            s += v;
        }
    }
    part[t] = s;
    __syncthreads();

    for (int off = 1; off < 1024; off <<= 1) {
        int v = (t >= off) ? part[t - off] : 0;
        __syncthreads();
        part[t] += v;
        __syncthreads();
    }

    for (int j = t; j < NN; j += 1024) {
        int c = j / SCAN_CH;
        int off = (c > 0) ? part[c - 1] : 0;
        int r = off + vals[j];
        g_rowptr[j] = r;
        g_cursor[j] = r;
    }
    if (t == 0) g_rowptr[NN] = part[1023];
}

__global__ void scatter_kernel(const int* __restrict__ src, const int* __restrict__ dst) {
    int e = blockIdx.x*blockDim.x + threadIdx.x;
    if (e < EE) {
        int p = atomicAdd(&g_cursor[dst[e]], 1);
        g_csrsrc[p] = src[e];
    }
}

// ---------------- tensor-core GEMM (3-stage cp.async, swizzled smem, 1 sync/chunk) ----
__device__ __forceinline__ void ldm_x4(u32 addr, u32& r0, u32& r1, u32& r2, u32& r3) {
    asm volatile("ldmatrix.sync.aligned.m8n8.x4.shared.b16 {%0,%1,%2,%3}, [%4];"
        : "=r"(r0), "=r"(r1), "=r"(r2), "=r"(r3) : "r"(addr));
}

__device__ __forceinline__ void mma16816(float* c, const u32* a, const u32* b) {
    asm volatile(
        "mma.sync.aligned.m16n8k16.row.col.f32.bf16.bf16.f32 "
        "{%0,%1,%2,%3}, {%4,%5,%6,%7}, {%8,%9}, {%0,%1,%2,%3};"
        : "+f"(c[0]), "+f"(c[1]), "+f"(c[2]), "+f"(c[3])
        : "r"(a[0]), "r"(a[1]), "r"(a[2]), "r"(a[3]), "r"(b[0]), "r"(b[1]));
}

#define CP16(dst, src, sz) asm volatile( \
    "cp.async.cg.shared.global [%0], [%1], 16, %2;" :: "r"(dst), "l"(src), "r"(sz))
#define CP_COMMIT() asm volatile("cp.async.commit_group;")
#define CP_WAIT1()  asm volatile("cp.async.wait_group 1;")
#define CP_WAIT0()  asm volatile("cp.async.wait_group 0;")

#define A_BYTES (128*64)
#define B_BYTES (64*64)
#define STAGE_BYTES (2*A_BYTES + 2*B_BYTES)   /* 24576 */
#define NSTAGE 3
#define SWZ(row, c) (((u32)(row) << 6) + (u32)(((c) ^ (((row) >> 1) & 3)) << 4))

#define GISSUE(kc, st) { \
    int kb = ((kc) << 5) + cq * 8; \
    u32 sbase = smem_u + (u32)((st) * STAGE_BYTES); \
    CP16(sbase + aoff0,                       Ahi + (size_t)arow0c * K + kb, szA0); \
    CP16(sbase + aoff0 + 4096u,               Ahi + (size_t)arow1c * K + kb, szA1); \
    CP16(sbase + (u32)A_BYTES + aoff0,        Alo + (size_t)arow0c * K + kb, szA0); \
    CP16(sbase + (u32)A_BYTES + aoff0 + 4096u, Alo + (size_t)arow1c * K + kb, szA1); \
    CP16(sbase + (u32)(2*A_BYTES) + boff,     Bhi + (size_t)(n0 + br0) * K + kb, 16); \
    CP16(sbase + (u32)(2*A_BYTES + B_BYTES) + boff, Blo + (size_t)(n0 + br0) * K + kb, 16); \
}

__global__ void __launch_bounds__(256, 3) gemm_bf16split(
    int M, int Nd, int K, int col_base,
    const __nv_bfloat16* __restrict__ Ahi, const __nv_bfloat16* __restrict__ Alo,
    const __nv_bfloat16* __restrict__ Bhi, const __nv_bfloat16* __restrict__ Blo,
    const float* __restrict__ bias, const float* __restrict__ resid,
    float* __restrict__ C, __nv_bfloat16* __restrict__ Chi, __nv_bfloat16* __restrict__ Clo,
    int do_relu,
    float* __restrict__ gatep, const float* __restrict__ p2w,
    float* __restrict__ snsp, float* __restrict__ sndp,
    const float* __restrict__ ansp, const float* __restrict__ andp,
    int zero_aux)
{
    extern __shared__ __nv_bfloat16 smem[];

    const int tid  = threadIdx.x;
    const int lane = tid & 31;
    const int w    = tid >> 5;
    const int wm   = w & 3;
    const int wn   = w >> 2;
    const int m0   = blockIdx.x * 128;
    const int n0   = blockIdx.y * 64;
    const int nk   = K >> 5;

    float acc[2][4][4];
#pragma unroll
    for (int a = 0; a < 2; a++)
#pragma unroll
        for (int b = 0; b < 4; b++)
#pragma unroll
            for (int c = 0; c < 4; c++) acc[a][b][c] = 0.f;

    const u32 smem_u = (u32)__cvta_generic_to_shared(smem);

    const int a_row_in = (lane & 7) + ((lane >> 3) & 1) * 8;
    const int a_chalf  = lane >> 4;
    const int b_sub    = lane >> 3;
    const int b_row_in = (lane & 7) + (b_sub >> 1) * 8;
    const int b_chalf  = b_sub & 1;

    const int ar0 = tid >> 2;
    const int cq  = tid & 3;
    const int br0 = ar0;
    const int arow0 = m0 + ar0;
    const int arow1 = m0 + ar0 + 64;
    const int arow0c = (arow0 < M) ? arow0 : (M - 1);
    const int arow1c = (arow1 < M) ? arow1 : (M - 1);
    const u32 szA0 = (arow0 < M) ? 16u : 0u;
    const u32 szA1 = (arow1 < M) ? 16u : 0u;
    const u32 aoff0 = SWZ(ar0, cq);
    const u32 boff  = SWZ(br0, cq);

    GISSUE(0, 0);
    CP_COMMIT();
    if (nk > 1) { GISSUE(1, 1); CP_COMMIT(); }

    int cur = 0;
    for (int kc = 0; kc < nk; kc++) {
        if (kc + 1 < nk) { CP_WAIT1(); } else { CP_WAIT0(); }
        __syncthreads();

        if (kc + 2 < nk) {
            int st = kc + 2 - ((kc + 2) / NSTAGE) * NSTAGE;
            GISSUE(kc + 2, st);
            CP_COMMIT();
        }

        const u32 stbase = smem_u + (u32)(cur * STAGE_BYTES);
#pragma unroll
        for (int ks = 0; ks < 2; ks++) {
            u32 Af[2][2][4];
            u32 Bf[2][4][2];
#pragma unroll
            for (int hl = 0; hl < 2; hl++) {
                const u32 abase = stbase + (u32)(hl * A_BYTES);
#pragma unroll
                for (int mt = 0; mt < 2; mt++) {
                    int row = wm * 32 + mt * 16 + a_row_in;
                    u32 addr = abase + SWZ(row, ks * 2 + a_chalf);
                    ldm_x4(addr, Af[hl][mt][0], Af[hl][mt][1], Af[hl][mt][2], Af[hl][mt][3]);
                }
                const u32 bbase = stbase + (u32)(2 * A_BYTES + hl * B_BYTES);
#pragma unroll
                for (int pr = 0; pr < 2; pr++) {
                    int row = wn * 32 + pr * 16 + b_row_in;
                    u32 addr2 = bbase + SWZ(row, ks * 2 + b_chalf);
                    u32 q0, q1, q2, q3;
                    ldm_x4(addr2, q0, q1, q2, q3);
                    Bf[hl][pr * 2 + 0][0] = q0; Bf[hl][pr * 2 + 0][1] = q1;
                    Bf[hl][pr * 2 + 1][0] = q2; Bf[hl][pr * 2 + 1][1] = q3;
                }
            }
#pragma unroll
            for (int term = 0; term < 3; term++) {
                const int ahl = (term == 2) ? 1 : 0;
                const int bhl = (term == 1) ? 1 : 0;
#pragma unroll
                for (int mt = 0; mt < 2; mt++)
#pragma unroll
                    for (int nt = 0; nt < 4; nt++)
                        mma16816(acc[mt][nt], Af[ahl][mt], Bf[bhl][nt]);
            }
        }
        cur++; if (cur == NSTAGE) cur = 0;
    }

    // epilogue
    const int gr = lane >> 2;
    const int gc = (lane & 3) * 2;
    const int head = (col_base + n0 + wn * 32) >> 7;
#pragma unroll
    for (int mt = 0; mt < 2; mt++) {
#pragma unroll
        for (int half = 0; half < 2; half++) {
            int m = m0 + wm * 32 + mt * 16 + gr + half * 8;
            if (m >= M) continue;
            float gpart = 0.f, ps = 0.f, pt = 0.f;
#pragma unroll
            for (int nt = 0; nt < 4; nt++) {
                int gn = col_base + n0 + wn * 32 + nt * 8 + gc;
                float v0 = acc[mt][nt][half * 2 + 0];
                float v1 = acc[mt][nt][half * 2 + 1];
                if (bias) { v0 += bias[gn]; v1 += bias[gn + 1]; }
                if (do_relu) { v0 = fmaxf(v0, 0.f); v1 = fmaxf(v1, 0.f); }
                if (resid) {
                    v0 += resid[(size_t)m * Nd + gn];
                    v1 += resid[(size_t)m * Nd + gn + 1];
                }
                if (gatep) {
                    gpart += v0 * __ldg(p2w + gn) + v1 * __ldg(p2w + gn + 1);
                }
                if (snsp) {
                    ps += v0 * __ldg(ansp + gn) + v1 * __ldg(ansp + gn + 1);
                    pt += v0 * __ldg(andp + gn) + v1 * __ldg(andp + gn + 1);
                }
                if (C) {
                    float2 vv; vv.x = v0; vv.y = v1;
                    *(float2*)(C + (size_t)m * Nd + gn) = vv;
                }
                if (Chi) {
                    __nv_bfloat16 h0, l0, h1, l1;
                    split_bf16(v0, h0, l0);
                    split_bf16(v1, h1, l1);
                    __nv_bfloat162 hh; hh.x = h0; hh.y = h1;
                    __nv_bfloat162 ll; ll.x = l0; ll.y = l1;
                    *(__nv_bfloat162*)(Chi + (size_t)m * Nd + gn) = hh;
                    *(__nv_bfloat162*)(Clo + (size_t)m * Nd + gn) = ll;
                }
            }
            if (gatep) atomicAdd(gatep + m, gpart);
            if (snsp) {
                atomicAdd(snsp + m * 3 + head, ps);
                atomicAdd(sndp + m * 3 + head, pt);
            }
            if (zero_aux) {
                g_sns[m * 3 + 0] = 0.f; g_sns[m * 3 + 1] = 0.f; g_sns[m * 3 + 2] = 0.f;
                g_snd[m * 3 + 0] = 0.f; g_snd[m * 3 + 1] = 0.f; g_snd[m * 3 + 2] = 0.f;
                g_gate[m] = 0.f;
            }
        }
    }
}

// ---------------- edge softmax + aggregation: one warp per dst node ----------------
__device__ __forceinline__ float leaky(float x) { return x > 0.f ? x : NEG_SLOPE * x; }

__global__ void gat_edge_kernel() {
    int v = (blockIdx.x * blockDim.x + threadIdx.x) >> 5;
    int lane = threadIdx.x & 31;
    if (v >= NN) return;
    int beg = g_rowptr[v], end = g_rowptr[v + 1];
    float snd0 = g_snd[v * 3 + 0], snd1 = g_snd[v * 3 + 1], snd2 = g_snd[v * 3 + 2];

    float m0 = -1e30f, m1 = -1e30f, m2 = -1e30f;
    for (int e = beg + lane; e < end; e += 32) {
        int s = g_csrsrc[e];
        m0 = fmaxf(m0, leaky(g_sns[s * 3 + 0] + snd0));
        m1 = fmaxf(m1, leaky(g_sns[s * 3 + 1] + snd1));
        m2 = fmaxf(m2, leaky(g_sns[s * 3 + 2] + snd2));
    }
#pragma unroll
    for (int o = 16; o; o >>= 1) {
        m0 = fmaxf(m0, __shfl_xor_sync(0xffffffffu, m0, o));
        m1 = fmaxf(m1, __shfl_xor_sync(0xffffffffu, m1, o));
        m2 = fmaxf(m2, __shfl_xor_sync(0xffffffffu, m2, o));
    }

    float acc[12];
#pragma unroll
    for (int j = 0; j < 12; j++) acc[j] = 0.f;
    float ws0 = 0.f, ws1 = 0.f, ws2 = 0.f;

    for (int e = beg; e < end; e++) {
        int s = g_csrsrc[e];
        float w0 = __expf(leaky(g_sns[s * 3 + 0] + snd0) - m0);
        float w1 = __expf(leaky(g_sns[s * 3 + 1] + snd1) - m1);
        float w2 = __expf(leaky(g_sns[s * 3 + 2] + snd2) - m2);
        ws0 += w0; ws1 += w1; ws2 += w2;
        const float* hr = g_h + (size_t)s * HD;
#pragma unroll
        for (int j = 0; j < 12; j++) {
            float wv = (j < 4) ? w0 : (j < 8) ? w1 : w2;
            acc[j] += wv * hr[j * 32 + lane];
        }
    }

    float r0 = ws0 > 0.f ? 1.f / ws0 : 0.f;
    float r1 = ws1 > 0.f ? 1.f / ws1 : 0.f;
    float r2 = ws2 > 0.f ? 1.f / ws2 : 0.f;
    __nv_bfloat16* ah = g_agghi + (size_t)v * HD;
    __nv_bfloat16* al = g_agglo + (size_t)v * HD;
#pragma unroll
    for (int j = 0; j < 12; j++) {
        float rv = (j < 4) ? r0 : (j < 8) ? r1 : r2;
        float val = acc[j] * rv;
        __nv_bfloat16 h, l; split_bf16(val, h, l);
        ah[j * 32 + lane] = h;
        al[j * 32 + lane] = l;
    }
}

// ---------------- global attention pooling ----------------
__global__ void pool_kernel(const float* __restrict__ feat, float* __restrict__ out, float scale) {
    int g = blockIdx.x;
    int d = threadIdx.x;
    int s = g_gstart[g], e = g_gend[g];
    __shared__ float red[128];

    float m = -1e30f;
    for (int i = s + d; i < e; i += 128) m = fmaxf(m, g_gate[i]);
    red[d] = m; __syncthreads();
    for (int o = 64; o; o >>= 1) { if (d < o) red[d] = fmaxf(red[d], red[d + o]); __syncthreads(); }
    m = red[0]; __syncthreads();

    float sum = 0.f;
    for (int i = s + d; i < e; i += 128) sum += __expf(g_gate[i] - m);
    red[d] = sum; __syncthreads();
    for (int o = 64; o; o >>= 1) { if (d < o) red[d] += red[d + o]; __syncthreads(); }
    sum = red[0]; __syncthreads();

    float accv = 0.f;
    for (int i = s; i < e; i++) {
        float wv = __expf(g_gate[i] - m);
        accv += wv * feat[(size_t)i * DD + d];
    }
    if (e > s && sum > 0.f) out[g * DD + d] += scale * accv / sum;
}

// ---------------- launch ----------------
extern "C" void kernel_launch(void* const* d_in, const int* in_sizes, int n_in,
                              void* d_out, int out_size)
{
    const float* feat    = (const float*)d_in[0];
    const int*   src     = (const int*)d_in[1];
    const int*   dst     = (const int*)d_in[2];
    const int*   gid     = (const int*)d_in[3];
    const float* fc_w    = (const float*)d_in[4];
    const float* a_ns    = (const float*)d_in[5];
    const float* a_nd    = (const float*)d_in[6];
    const float* trans_w = (const float*)d_in[7];
    const float* trans_b = (const float*)d_in[8];
    const float* p1_w    = (const float*)d_in[9];
    const float* p1_b    = (const float*)d_in[10];
    const float* p2_w    = (const float*)d_in[11];
    const float* p2_b    = (const float*)d_in[12];
    (void)p2_b;  // per-graph softmax over gate is shift-invariant
    float* out = (float*)d_out;

    static cudaStream_t sB = 0;
    static cudaEvent_t evA = 0, evCSR = 0, evG2[LL], evPool[LL];
    if (!sB) {
        cudaStreamCreateWithFlags(&sB, cudaStreamNonBlocking);
        cudaEventCreateWithFlags(&evA, cudaEventDisableTiming);
        cudaEventCreateWithFlags(&evCSR, cudaEventDisableTiming);
        for (int d = 0; d < LL; d++) {
            cudaEventCreateWithFlags(&evG2[d], cudaEventDisableTiming);
            cudaEventCreateWithFlags(&evPool[d], cudaEventDisableTiming);
        }
    }

    float *p_h, *p_featA, *p_featB, *p_gate, *p_sns, *p_snd;
    cudaGetSymbolAddress((void**)&p_h, g_h);
    cudaGetSymbolAddress((void**)&p_featA, g_featA);
    cudaGetSymbolAddress((void**)&p_featB, g_featB);
    cudaGetSymbolAddress((void**)&p_gate, g_gate);
    cudaGetSymbolAddress((void**)&p_sns, g_sns);
    cudaGetSymbolAddress((void**)&p_snd, g_snd);

    __nv_bfloat16 *p_fhiA, *p_floA, *p_fhiB, *p_floB, *p_agghi, *p_agglo;
    __nv_bfloat16 *p_wfchi, *p_wfclo, *p_wtrhi, *p_wtrlo, *p_wp1hi, *p_wp1lo;
    cudaGetSymbolAddress((void**)&p_fhiA, g_fhiA);
    cudaGetSymbolAddress((void**)&p_floA, g_floA);
    cudaGetSymbolAddress((void**)&p_fhiB, g_fhiB);
    cudaGetSymbolAddress((void**)&p_floB, g_floB);
    cudaGetSymbolAddress((void**)&p_agghi, g_agghi);
    cudaGetSymbolAddress((void**)&p_agglo, g_agglo);
    cudaGetSymbolAddress((void**)&p_wfchi, g_wfchi);
    cudaGetSymbolAddress((void**)&p_wfclo, g_wfclo);
    cudaGetSymbolAddress((void**)&p_wtrhi, g_wtrhi);
    cudaGetSymbolAddress((void**)&p_wtrlo, g_wtrlo);
    cudaGetSymbolAddress((void**)&p_wp1hi, g_wp1hi);
    cudaGetSymbolAddress((void**)&p_wp1lo, g_wp1lo);

    const int SMEM_GEMM = NSTAGE * STAGE_BYTES;   // 73728
    cudaFuncSetAttribute(gemm_bf16split, cudaFuncAttributeMaxDynamicSharedMemorySize, SMEM_GEMM);
    cudaFuncSetAttribute(scan_kernel, cudaFuncAttributeMaxDynamicSharedMemorySize, SCAN_SMEM);

    const int gx = (NN + 127) / 128;
    const int warpBlocks = (NN + 7) / 8;
    const int NCONV = LL*(HD*DD + DD*HD + TWO_D*DD);

    // main: copy+split input, zero state -> fork point
    copy_split_kernel<<<(NN * DD + 255) / 256, 256>>>(feat, out);
    cudaEventRecord(evA, 0);

    // side (joins capture via evA wait): hist+gbounds -> scan -> scatter
    cudaStreamWaitEvent(sB, evA, 0);
    histgb_kernel<<<(EE + 255) / 256, 256, 0, sB>>>(dst, gid);
    scan_kernel<<<1, 1024, SCAN_SMEM, sB>>>();
    scatter_kernel<<<(EE + 255) / 256, 256, 0, sB>>>(src, dst);
    cudaEventRecord(evCSR, sB);

    // main: weight converts, then layer-0 h-GEMM (overlaps side CSR chain)
    convw_kernel<<<(NCONV + 255) / 256, 256>>>(fc_w, trans_w, p1_w);
    gemm_bf16split<<<dim3(gx, HD / 64), 256, SMEM_GEMM>>>(NN, HD, DD, 0,
        p_fhiA, p_floA, p_wfchi, p_wfclo,
        (const float*)0, (const float*)0, p_h,
        (__nv_bfloat16*)0, (__nv_bfloat16*)0, 0,
        (float*)0, (const float*)0,
        p_sns, p_snd, a_ns, a_nd, 0);

    cudaStreamWaitEvent(0, evCSR, 0);   // CSR ready before first edge kernel

    for (int d = 0; d < LL; d++) {
        int pp = d & 1;
        float* fin  = pp ? p_featB : p_featA;
        float* fout = pp ? p_featA : p_featB;
        __nv_bfloat16* fouthi = pp ? p_fhiA : p_fhiB;
        __nv_bfloat16* foutlo = pp ? p_floA : p_floB;

        gat_edge_kernel<<<warpBlocks, 256>>>();

        // gemm2 zeroes g_gate/sns/snd -> wait for pool(d-1) (reads g_gate)
        if (d > 0) cudaStreamWaitEvent(0, evPool[d-1], 0);

        // fout = relu?(agg @ trans_w[d]^T + b) + fin  (+ bf16 split, + zero aux)
        gemm_bf16split<<<dim3(gx, DD / 64), 256, SMEM_GEMM>>>(NN, DD, HD, 0,
            p_agghi, p_agglo, p_wtrhi + (size_t)d * DD * HD, p_wtrlo + (size_t)d * DD * HD,
            trans_b + (size_t)d * DD, fin, fout, fouthi, foutlo, (d < LL - 1) ? 1 : 0,
            (float*)0, (const float*)0, (float*)0, (float*)0, (const float*)0, (const float*)0,
            1);
        cudaEventRecord(evG2[d], 0);

        // side: gate GEMM (p1/p2 MLP fused) -> pool(d), overlaps main's next work
        cudaStreamWaitEvent(sB, evG2[d], 0);
        gemm_bf16split<<<dim3(gx, TWO_D / 64), 256, SMEM_GEMM, sB>>>(NN, TWO_D, DD, 0,
            fouthi, foutlo, p_wp1hi + (size_t)d * TWO_D * DD, p_wp1lo + (size_t)d * TWO_D * DD,
            p1_b + (size_t)d * TWO_D, (const float*)0, (float*)0,
            (__nv_bfloat16*)0, (__nv_bfloat16*)0, 1,
            p_gate, p2_w + (size_t)d * TWO_D,
            (float*)0, (float*)0, (const float*)0, (const float*)0, 0);
        pool_kernel<<<GG, 128, 0, sB>>>(fout, out, 1.0f / LL);
        cudaEventRecord(evPool[d], sB);

        // main: next layer's h-GEMM (+ fused attn scores), overlaps gate/pool
        if (d < LL - 1) {
            gemm_bf16split<<<dim3(gx, HD / 64), 256, SMEM_GEMM>>>(NN, HD, DD, 0,
                fouthi, foutlo,
                p_wfchi + (size_t)(d+1) * HD * DD, p_wfclo + (size_t)(d+1) * HD * DD,
                (const float*)0, (const float*)0, p_h,
                (__nv_bfloat16*)0, (__nv_bfloat16*)0, 0,
                (float*)0, (const float*)0,
                p_sns, p_snd, a_ns + (size_t)(d+1) * HD, a_nd + (size_t)(d+1) * HD, 0);
        }
    }

    // join side-stream work back to main before return
    cudaStreamWaitEvent(0, evPool[LL-1], 0);
}